// round 13
// baseline (speedup 1.0000x reference)
#include <cuda_runtime.h>

// ============================================================================
// RNN_41936060678228: autoregressive LSTM wavefunction
// B=2048, L=512, F=64, K=2. Output = float32 amp only.
//
// Round-13: N-split, weights in REGISTERS. 128 CTAs x 128 threads (4 warps).
// Warp w owns gate-columns [64w,64w+64) for ALL 16 CTA samples; each lane
// permanently holds its column-pair's 64 Wh values as 64 ULL regs -> zero
// weight loads in the time loop. Per sample: 64 fma.rn.f32x2 (reg weights)
// x broadcast LDS.128 of duplicated {h,h}. Lane-pair shfl exchange for
// gates; producer-side logp partials via parity shfl trees; h double-
// buffered; 2 __syncthreads per step.
// ============================================================================

typedef unsigned long long ULL;

__device__ __align__(16) float g_Whp[64 * 256];
__device__ __align__(16) float g_u[2 * 256];
__device__ __align__(16) float g_wd[64];
__device__ float g_bd[1];

__device__ __forceinline__ ULL fma2(ULL a, ULL b, ULL c) {
    ULL d;
    asm("fma.rn.f32x2 %0, %1, %2, %3;" : "=l"(d) : "l"(a), "l"(b), "l"(c));
    return d;
}
__device__ __forceinline__ void upk2(float& lo, float& hi, ULL p) {
    asm("mov.b64 {%0, %1}, %2;" : "=f"(lo), "=f"(hi) : "l"(p));
}
__device__ __forceinline__ float tanhap(float x) {
    float t;
    asm("tanh.approx.f32 %0, %1;" : "=f"(t) : "f"(x));
    return t;
}
__device__ __forceinline__ float sigt(float x) {
    return fmaf(tanhap(0.5f * x), 0.5f, 0.5f);
}
__device__ __forceinline__ float softplusf(float x) {
    float ax = fabsf(x);
    return fmaxf(x, 0.0f) + __logf(1.0f + __expf(-ax));
}

// ---------------------------------------------------------------------------
// Prep: gate-interleave Wh columns: pj = 4*n + gate (i,f,g,o), j = gate*64+n.
// ---------------------------------------------------------------------------
__global__ void prep_kernel(const float* __restrict__ W0, const float* __restrict__ b0,
                            const float* __restrict__ Wi, const float* __restrict__ Wh,
                            const float* __restrict__ bh, const float* __restrict__ Wa,
                            const float* __restrict__ ba) {
    int idx = blockIdx.x * blockDim.x + threadIdx.x;
    if (idx < 16384) {
        int k = idx >> 8, pj = idx & 255;
        int n = pj >> 2, gate = pj & 3;
        g_Whp[k * 256 + pj] = Wh[k * 256 + gate * 64 + n];
    } else if (idx < 16896) {
        int t = idx - 16384;
        int tok = t >> 8, pj = t & 255;
        int n = pj >> 2, gate = pj & 3;
        int j = gate * 64 + n;
        float acc = bh[j];
        for (int f = 0; f < 64; f++)
            acc += (W0[tok * 64 + f] + b0[f]) * Wi[f * 256 + j];
        g_u[tok * 256 + pj] = acc;
    } else if (idx < 16960) {
        int n = idx - 16896;
        g_wd[n] = Wa[n * 2 + 1] - Wa[n * 2 + 0];
    } else if (idx == 16960) {
        g_bd[0] = ba[1] - ba[0];
    }
}

// ---------------------------------------------------------------------------
// Row pitch for h buffers: 132 floats (528B, 16B-aligned, bank-staggered).
// ---------------------------------------------------------------------------
#define HP 132

__global__ __launch_bounds__(128, 1) void lstm_kernel(const int* __restrict__ s,
                                                      float* __restrict__ out,
                                                      int B, int L) {
    __shared__ float sU[512];
    __shared__ float sWd[64];
    __shared__ __align__(16) float sHd[2][16 * HP];   // {h,h} dup, ping-pong
    __shared__ float sD[4][16];                       // per-warp logp partials
    __shared__ int   sTok[16];

    int tid = threadIdx.x, lane = tid & 31, w = tid >> 5;

    for (int i = tid; i < 512; i += 128) sU[i] = g_u[i];
    if (tid < 64) sWd[tid] = g_wd[tid];
    {
        float* hz = &sHd[0][0];
        for (int i = tid; i < 2 * 16 * HP; i += 128) hz[i] = 0.0f;
    }
    if (tid < 16) sTok[tid] = 0;
    __syncthreads();

    // ---- weights into registers: lane's column pair, all 64 k ----
    ULL wreg[64];
#pragma unroll
    for (int k = 0; k < 64; k++)
        wreg[k] = *(const ULL*)(g_Whp + k * 256 + w * 64 + lane * 2);

    const float bd  = g_bd[0];
    const int   n_cell = w * 16 + (lane >> 1);
    const float wdn = sWd[n_cell];
    const int   cell2 = n_cell * 2;            // dup-pair float offset in h row
    const int   upair = w * 64 + lane * 2;     // float offset of pair in u row
    const bool  evenlane = ((lane & 1) == 0);

    float c[8];
#pragma unroll
    for (int j = 0; j < 8; j++) c[j] = 0.0f;
    float amp[4] = {0.f, 0.f, 0.f, 0.f};

    int base = blockIdx.x * 16;
    const int* srow[4];
#pragma unroll
    for (int j = 0; j < 4; j++) {
        long long gi = min(base + w * 4 + j, B - 1);
        srow[j] = s + gi * L;
    }

    for (int t = 0; t < L; t++) {
        const float* hcur = &sHd[t & 1][0];
        float*       hnxt = &sHd[(t + 1) & 1][0];

        // spins for this warp's 4 output samples (used after sync1)
        int sp0 = __ldg(srow[0] + t), sp1 = __ldg(srow[1] + t);
        int sp2 = __ldg(srow[2] + t), sp3 = __ldg(srow[3] + t);

        float pd[8];

        // ---- per-sample fused: kloop -> shfl exchange -> gates -> h store ----
#pragma unroll
        for (int ss = 0; ss < 16; ss++) {
            int tok = sTok[ss];
            ULL acc = *(const ULL*)(sU + (tok << 8) + upair);
            const float* hrow = hcur + ss * HP;
#pragma unroll
            for (int kb = 0; kb < 64; kb += 4) {
                ulonglong2 Ha = *(const ulonglong2*)(hrow + 2 * kb);
                ulonglong2 Hb = *(const ulonglong2*)(hrow + 2 * kb + 4);
                acc = fma2(Ha.x, wreg[kb + 0], acc);
                acc = fma2(Ha.y, wreg[kb + 1], acc);
                acc = fma2(Hb.x, wreg[kb + 2], acc);
                acc = fma2(Hb.y, wreg[kb + 3], acc);
            }
            ULL accx = __shfl_xor_sync(0xffffffffu, acc, 1);

            float gi_, gf_, gg_, go_;
            if (ss < 8) { upk2(gi_, gf_, acc);  upk2(gg_, go_, accx); }
            else        { upk2(gg_, go_, acc);  upk2(gi_, gf_, accx); }

            bool active = (ss < 8) ? evenlane : !evenlane;
            float cn = fmaf(sigt(gf_), c[ss & 7], sigt(gi_) * tanhap(gg_));
            float hn = sigt(go_) * tanhap(cn);
            if (active) {
                c[ss & 7] = cn;
                *(float2*)(hnxt + ss * HP + cell2) = make_float2(hn, hn);
                pd[ss & 7] = hn * wdn;
            }
        }

        // ---- per-warp logp partials: parity shfl trees (both parities at once)
#pragma unroll
        for (int j = 0; j < 8; j++) {
            float v = pd[j];
            v += __shfl_xor_sync(0xffffffffu, v, 2);
            v += __shfl_xor_sync(0xffffffffu, v, 4);
            v += __shfl_xor_sync(0xffffffffu, v, 8);
            v += __shfl_xor_sync(0xffffffffu, v, 16);
            pd[j] = v;
        }
        if (lane == 0) {
#pragma unroll
            for (int j = 0; j < 8; j++) sD[w][j] = pd[j];
        } else if (lane == 1) {
#pragma unroll
            for (int j = 0; j < 8; j++) sD[w][8 + j] = pd[j];
        }
        __syncthreads();

        // ---- finalize this warp's 4 samples ----
        {
            int s0 = w * 4;
            float d0 = sD[0][s0+0] + sD[1][s0+0] + sD[2][s0+0] + sD[3][s0+0] + bd;
            float d1 = sD[0][s0+1] + sD[1][s0+1] + sD[2][s0+1] + sD[3][s0+1] + bd;
            float d2 = sD[0][s0+2] + sD[1][s0+2] + sD[2][s0+2] + sD[3][s0+2] + bd;
            float d3 = sD[0][s0+3] + sD[1][s0+3] + sD[2][s0+3] + sD[3][s0+3] + bd;
            amp[0] -= 0.5f * softplusf(sp0 ? -d0 : d0);
            amp[1] -= 0.5f * softplusf(sp1 ? -d1 : d1);
            amp[2] -= 0.5f * softplusf(sp2 ? -d2 : d2);
            amp[3] -= 0.5f * softplusf(sp3 ? -d3 : d3);
            if (lane == 0) {
                sTok[s0 + 0] = sp0; sTok[s0 + 1] = sp1;
                sTok[s0 + 2] = sp2; sTok[s0 + 3] = sp3;
            }
        }
        __syncthreads();
    }

    if (lane == 0) {
#pragma unroll
        for (int j = 0; j < 4; j++) {
            int o = base + w * 4 + j;
            if (o < B) out[o] = amp[j];
        }
    }
}

// ---------------------------------------------------------------------------
extern "C" void kernel_launch(void* const* d_in, const int* in_sizes, int n_in,
                              void* d_out, int out_size) {
    const int*   s  = (const int*)d_in[0];
    const float* W0 = (const float*)d_in[1];
    const float* b0 = (const float*)d_in[2];
    const float* Wi = (const float*)d_in[3];
    const float* Wh = (const float*)d_in[4];
    const float* bh = (const float*)d_in[5];
    const float* Wa = (const float*)d_in[6];
    const float* ba = (const float*)d_in[7];

    int B = out_size;
    int L = (B > 0) ? in_sizes[0] / B : 0;

    prep_kernel<<<67, 256>>>(W0, b0, Wi, Wh, bh, Wa, ba);

    int grid = (B + 15) / 16;
    lstm_kernel<<<grid, 128>>>(s, (float*)d_out, B, L);
}